// round 14
// baseline (speedup 1.0000x reference)
#include <cuda_runtime.h>
#include <cuda_bf16.h>
#include <cuda_fp16.h>
#include <math.h>
#include <stdint.h>

#define BATCH 8
#define CDIM  512
#define INNER 256
#define QKV   768
#define HEADS 8
#define DH    32
#define HH    96
#define WW    96
#define HW    9216   // 96*96

// ---------------- scratch (static device globals) ---------------------------
__device__ __half g_xf  [(size_t)BATCH * CDIM  * HW];   // LN(x) fp16
__device__ __half g_qkv1[(size_t)BATCH * QKV   * HW];   // after 1x1 (fp16)
__device__ __half g_qkv2[(size_t)BATCH * QKV   * HW];   // after dwconv3 (fp16)
__device__ __half g_af  [(size_t)BATCH * INNER * HW];   // attn+silu fp16
__device__ __half g_wh  [(size_t)QKV * CDIM];           // qkv weights fp16
__device__ __half g_owh [(size_t)CDIM * INNER];         // out weights fp16
__device__ float g_ksum [BATCH * INNER];
__device__ float g_krsum[BATCH * INNER];
__device__ float g_ctxp [(size_t)9 * BATCH * HEADS * DH * DH];

// ---------------- merged weight conversion + ksum zeroing -------------------
__global__ void convert_w_kernel(const float* __restrict__ qw,
                                 const float* __restrict__ kw,
                                 const float* __restrict__ vw,
                                 const float* __restrict__ ow) {
    int i = blockIdx.x * blockDim.x + threadIdx.x;  // 0 .. INNER*CDIM-1
    g_wh[i]                 = __float2half(qw[i]);
    g_wh[i + INNER*CDIM]    = __float2half(kw[i]);
    g_wh[i + 2*INNER*CDIM]  = __float2half(vw[i]);
    g_owh[i]                = __float2half(ow[i]);    // CDIM*INNER == INNER*CDIM
    if (i < BATCH * INNER) g_ksum[i] = 0.f;           // zero each replay
}

// ---------------- input channel LN (smem-buffered, single pass) -------------
__global__ void ln_in_kernel(const float* __restrict__ x,
                             const float* __restrict__ g) {
    extern __shared__ float s[];            // [512][33]
    __shared__ float s_mean[32], s_r[32];
    int t = threadIdx.x;
    int pos0 = blockIdx.x * 32;
    int b = pos0 / HW;
    int hw0 = pos0 - b * HW;
    int lane = t & 31, crow = t >> 5;
    #pragma unroll 8
    for (int it = 0; it < 64; it++) {
        int c = crow + it * 8;
        s[c * 33 + lane] = x[((size_t)b * CDIM + c) * HW + hw0 + lane];
    }
    __syncthreads();
    int p = t >> 3, sub = t & 7;            // 8 threads per position
    float sm = 0.f, sq = 0.f;
    #pragma unroll 8
    for (int j = 0; j < 64; j++) {
        float v = s[(sub + j * 8) * 33 + p];
        sm += v; sq += v * v;
    }
    #pragma unroll
    for (int off = 4; off > 0; off >>= 1) {
        sm += __shfl_xor_sync(0xffffffffu, sm, off);
        sq += __shfl_xor_sync(0xffffffffu, sq, off);
    }
    float mean = sm * (1.f / CDIM);
    float var  = sq * (1.f / CDIM) - mean * mean;
    float r = rsqrtf(var + 1e-5f);
    if (sub == 0) { s_mean[p] = mean; s_r[p] = r; }
    __syncthreads();
    float m2 = s_mean[lane], r2 = s_r[lane];
    #pragma unroll 8
    for (int it = 0; it < 64; it++) {
        int c = crow + it * 8;
        float y = (s[c * 33 + lane] - m2) * r2 * g[c];
        g_xf[((size_t)b * CDIM + c) * HW + hw0 + lane] = __float2half(y);
    }
}

// ---------------- shared GEMM helpers ---------------------------------------
__device__ __forceinline__ uint32_t sptr(const void* p) {
    return (uint32_t)__cvta_generic_to_shared(p);
}
__device__ __forceinline__ void cp_async16(void* sm, const void* gm) {
    asm volatile("cp.async.cg.shared.global [%0], [%1], 16;\n"
                 :: "r"(sptr(sm)), "l"(gm));
}
__device__ __forceinline__ void ldsm_x4(uint32_t* r, uint32_t a) {
    asm volatile("ldmatrix.sync.aligned.m8n8.x4.shared.b16 {%0,%1,%2,%3}, [%4];"
                 : "=r"(r[0]), "=r"(r[1]), "=r"(r[2]), "=r"(r[3]) : "r"(a));
}
__device__ __forceinline__ void ldsm_x2t(uint32_t* r, uint32_t a) {
    asm volatile("ldmatrix.sync.aligned.m8n8.x2.trans.shared.b16 {%0,%1}, [%2];"
                 : "=r"(r[0]), "=r"(r[1]) : "r"(a));
}
__device__ __forceinline__ void mma_f16(float* c, const uint32_t* a, const uint32_t* b) {
    asm volatile("mma.sync.aligned.m16n8k16.row.col.f32.f16.f16.f32 "
                 "{%0,%1,%2,%3},{%4,%5,%6,%7},{%8,%9},{%0,%1,%2,%3};"
                 : "+f"(c[0]), "+f"(c[1]), "+f"(c[2]), "+f"(c[3])
                 : "r"(a[0]), "r"(a[1]), "r"(a[2]), "r"(a[3]), "r"(b[0]), "r"(b[1]));
}

// ---------------- GEMM 1: qkv = W @ LN(x), tile 128x128x64, fp16 out --------
__global__ void __launch_bounds__(256) gemm_qkv_kernel() {
    constexpr int M = QKV, K = CDIM, N = HW;
    constexpr int BM = 128, BN = 128, BK = 64;
    constexpr int AP = BK + 8;      // 72
    constexpr int BP = BN + 8;      // 136
    constexpr int A_SZ = BM * AP;
    constexpr int B_SZ = BK * BP;
    constexpr int STAGE = A_SZ + B_SZ;
    constexpr int KC = K / BK;
    extern __shared__ __half smem[];

    const __half* W = g_wh;
    int b = blockIdx.z;
    const __half* XfB = g_xf + (size_t)b * K * N;
    __half* Yb = g_qkv1 + (size_t)b * M * N;
    int tm0 = blockIdx.y * BM;
    int tn0 = blockIdx.x * BN;
    int t = threadIdx.x;
    int lane = t & 31, warp = t >> 5;
    int wm = (warp & 1) * 64, wn = (warp >> 1) * 32;

    auto load_stage = [&](int kc, int s) {
        __half* sa = smem + (size_t)s * STAGE;
        __half* sb = sa + A_SZ;
        int k0 = kc * BK;
        #pragma unroll
        for (int i = 0; i < 4; i++) {
            int c = t + i * 256;
            int m  = c >> 3, kk = (c & 7) * 8;
            cp_async16(&sa[m * AP + kk], &W[(size_t)(tm0 + m) * K + k0 + kk]);
            int kr = c >> 4, nn = (c & 15) * 8;
            cp_async16(&sb[kr * BP + nn], &XfB[(size_t)(k0 + kr) * N + tn0 + nn]);
        }
        asm volatile("cp.async.commit_group;");
    };

    float acc[4][4][4];
    #pragma unroll
    for (int i = 0; i < 4; i++)
        #pragma unroll
        for (int j = 0; j < 4; j++)
            #pragma unroll
            for (int r = 0; r < 4; r++) acc[i][j][r] = 0.f;

    load_stage(0, 0);
    for (int kc = 0; kc < KC; kc++) {
        int s = kc & 1;
        asm volatile("cp.async.wait_group 0;");
        __syncthreads();
        if (kc + 1 < KC) load_stage(kc + 1, s ^ 1);

        __half* sa = smem + (size_t)s * STAGE;
        __half* sb = sa + A_SZ;

        #pragma unroll
        for (int ks = 0; ks < 4; ks++) {
            uint32_t bx[4][2];
            int brow = ks * 16 + (lane & 15);
            #pragma unroll
            for (int nt = 0; nt < 4; nt++)
                ldsm_x2t(bx[nt], sptr(&sb[brow * BP + wn + nt * 8]));
            uint32_t a[4][4];
            int arow = lane & 15;
            int acol = ks * 16 + (lane >> 4) * 8;
            #pragma unroll
            for (int mt = 0; mt < 4; mt++)
                ldsm_x4(a[mt], sptr(&sa[(wm + mt * 16 + arow) * AP + acol]));
            #pragma unroll
            for (int mt = 0; mt < 4; mt++)
                #pragma unroll
                for (int nt = 0; nt < 4; nt++)
                    mma_f16(acc[mt][nt], a[mt], bx[nt]);
        }
    }

    #pragma unroll
    for (int mt = 0; mt < 4; mt++)
        #pragma unroll
        for (int nt = 0; nt < 4; nt++) {
            int m = tm0 + wm + mt * 16 + (lane >> 2);
            int n = tn0 + wn + nt * 8 + (lane & 3) * 2;
            *(__half2*)&Yb[(size_t)m * N + n] =
                __floats2half2_rn(acc[mt][nt][0], acc[mt][nt][1]);
            *(__half2*)&Yb[(size_t)(m + 8) * N + n] =
                __floats2half2_rn(acc[mt][nt][2], acc[mt][nt][3]);
        }
}

// ---------------- GEMM 2 + output LN fused: tile 512x32x64 ------------------
// One CTA computes ALL 512 output channels for 32 positions, then performs the
// channel LayerNorm in smem and writes the final fp32 output directly.
__global__ void __launch_bounds__(256) gemm_out_ln_kernel(
        const float* __restrict__ gamma, float* __restrict__ out) {
    constexpr int M = CDIM, K = INNER, N = HW;
    constexpr int BN = 32, BK = 64;
    constexpr int AP = BK + 8;      // 72
    constexpr int BP = BN + 8;      // 40
    constexpr int A_SZ = M * AP;    // 36864 halves
    constexpr int B_SZ = BK * BP;   // 2560 halves
    constexpr int STAGE = A_SZ + B_SZ;   // 39424 halves = 78848 B
    constexpr int KC = K / BK;      // 4
    extern __shared__ __half smem[];
    __shared__ float s_mean[32], s_r[32];

    int b = blockIdx.y;
    int hw0 = blockIdx.x * BN;
    const __half* XfB = g_af + (size_t)b * K * N;
    int t = threadIdx.x;
    int lane = t & 31, warp = t >> 5;
    int wm = warp * 64;

    auto load_stage = [&](int kc, int s) {
        __half* sa = smem + (size_t)s * STAGE;
        __half* sb = sa + A_SZ;
        int k0 = kc * BK;
        #pragma unroll
        for (int i = 0; i < 16; i++) {       // A: 4096 chunks
            int c = t + i * 256;
            int m  = c >> 3, kk = (c & 7) * 8;
            cp_async16(&sa[m * AP + kk], &g_owh[(size_t)m * K + k0 + kk]);
        }
        {                                     // B: 256 chunks
            int kr = t >> 2, nn = (t & 3) * 8;
            cp_async16(&sb[kr * BP + nn], &XfB[(size_t)(k0 + kr) * N + hw0 + nn]);
        }
        asm volatile("cp.async.commit_group;");
    };

    float acc[4][4][4];
    #pragma unroll
    for (int i = 0; i < 4; i++)
        #pragma unroll
        for (int j = 0; j < 4; j++)
            #pragma unroll
            for (int r = 0; r < 4; r++) acc[i][j][r] = 0.f;

    load_stage(0, 0);
    for (int kc = 0; kc < KC; kc++) {
        int s = kc & 1;
        asm volatile("cp.async.wait_group 0;");
        __syncthreads();
        if (kc + 1 < KC) load_stage(kc + 1, s ^ 1);

        __half* sa = smem + (size_t)s * STAGE;
        __half* sb = sa + A_SZ;

        #pragma unroll
        for (int ks = 0; ks < 4; ks++) {
            uint32_t bx[4][2];
            int brow = ks * 16 + (lane & 15);
            #pragma unroll
            for (int nt = 0; nt < 4; nt++)
                ldsm_x2t(bx[nt], sptr(&sb[brow * BP + nt * 8]));
            uint32_t a[4][4];
            int arow = lane & 15;
            int acol = ks * 16 + (lane >> 4) * 8;
            #pragma unroll
            for (int mt = 0; mt < 4; mt++)
                ldsm_x4(a[mt], sptr(&sa[(wm + mt * 16 + arow) * AP + acol]));
            #pragma unroll
            for (int mt = 0; mt < 4; mt++)
                #pragma unroll
                for (int nt = 0; nt < 4; nt++)
                    mma_f16(acc[mt][nt], a[mt], bx[nt]);
        }
    }
    __syncthreads();                 // all warps done reading stage smem

    // stage z (fp32) into smem [512][33]
    float* sf = (float*)smem;
    #pragma unroll
    for (int mt = 0; mt < 4; mt++)
        #pragma unroll
        for (int nt = 0; nt < 4; nt++) {
            int m = wm + mt * 16 + (lane >> 2);
            int n = nt * 8 + (lane & 3) * 2;
            sf[m * 33 + n]           = acc[mt][nt][0];
            sf[m * 33 + n + 1]       = acc[mt][nt][1];
            sf[(m + 8) * 33 + n]     = acc[mt][nt][2];
            sf[(m + 8) * 33 + n + 1] = acc[mt][nt][3];
        }
    __syncthreads();

    // channel LN over the 512 channels (identical math to the old ln_out)
    int p = t >> 3, sub = t & 7;
    float sm = 0.f, sq = 0.f;
    #pragma unroll 8
    for (int j = 0; j < 64; j++) {
        float v = sf[(sub + j * 8) * 33 + p];
        sm += v; sq += v * v;
    }
    #pragma unroll
    for (int off = 4; off > 0; off >>= 1) {
        sm += __shfl_xor_sync(0xffffffffu, sm, off);
        sq += __shfl_xor_sync(0xffffffffu, sq, off);
    }
    float mean = sm * (1.f / CDIM);
    float var  = sq * (1.f / CDIM) - mean * mean;
    float r = rsqrtf(var + 1e-5f);
    if (sub == 0) { s_mean[p] = mean; s_r[p] = r; }
    __syncthreads();
    int lane2 = t & 31, crow = t >> 5;
    float m2 = s_mean[lane2], r2 = s_r[lane2];
    #pragma unroll 8
    for (int it = 0; it < 64; it++) {
        int c = crow + it * 8;
        out[((size_t)b * CDIM + c) * HW + hw0 + lane2] =
            (sf[c * 33 + lane2] - m2) * r2 * gamma[c];
    }
}

// ---------------- depthwise 3x3: fp16 raw smem, rolling window, fused ksum --
__global__ void dwconv3_kernel(const float* __restrict__ qwd,
                               const float* __restrict__ kwd,
                               const float* __restrict__ vwd) {
    __shared__ __half s[50][112];
    __shared__ float red[384];
    int bc = blockIdx.x;              // b*QKV + c
    int half_id = blockIdx.y;         // 0: rows 0-47, 1: rows 48-95
    int h0 = half_id * 48;
    int c = bc % QKV;
    const float* wp = (c < 256) ? (qwd + c * 9)
                    : (c < 512) ? (kwd + (c - 256) * 9)
                                : (vwd + (c - 512) * 9);
    float w0 = wp[0], w1 = wp[1], w2 = wp[2];
    float w3 = wp[3], w4 = wp[4], w5 = wp[5];
    float w6 = wp[6], w7 = wp[7], w8 = wp[8];
    const __half* ip = g_qkv1 + (size_t)bc * HW;
    int tx = threadIdx.x;  // 0..95
    int ty = threadIdx.y;  // 0..3
    int tid = ty * 96 + tx;

    __half hz = __float2half(0.f);
    for (int r = tid; r < 50; r += 384) { s[r][7] = hz; s[r][104] = hz; }
    for (int i = tid; i < 50 * 12; i += 384) {
        int r = i / 12, c8 = i % 12;
        int hg = h0 - 1 + r;
        uint4* dst = (uint4*)&s[r][8 + c8 * 8];
        if (hg >= 0 && hg < HH) {
            *dst = *(const uint4*)(ip + (size_t)hg * WW + c8 * 8);
        } else {
            *dst = make_uint4(0u, 0u, 0u, 0u);
        }
    }
    __syncthreads();

    __half* op = g_qkv2 + (size_t)bc * HW + (size_t)h0 * WW;
    int wcol = 8 + tx;
    int base = ty * 12;               // local rows base..base+11
    bool is_k = (c >= INNER && c < 2 * INNER);
    float ksum = 0.f;

    float a0 = __half2float(s[base][wcol - 1]);
    float a1 = __half2float(s[base][wcol]);
    float a2 = __half2float(s[base][wcol + 1]);
    float b0 = __half2float(s[base + 1][wcol - 1]);
    float b1 = __half2float(s[base + 1][wcol]);
    float b2 = __half2float(s[base + 1][wcol + 1]);
    #pragma unroll
    for (int i = 0; i < 12; i++) {
        int hl = base + i;
        int r = hl + 2;
        float c0 = __half2float(s[r][wcol - 1]);
        float c1 = __half2float(s[r][wcol]);
        float c2 = __half2float(s[r][wcol + 1]);
        float acc = w0 * a0 + w1 * a1 + w2 * a2
                  + w3 * b0 + w4 * b1 + w5 * b2
                  + w6 * c0 + w7 * c1 + w8 * c2;
        __half hacc = __float2half(acc);
        op[hl * WW + tx] = hacc;
        if (is_k) ksum += __expf(__half2float(hacc));   // consistent with reader
        a0 = b0; a1 = b1; a2 = b2;
        b0 = c0; b1 = c1; b2 = c2;
    }

    if (is_k) {
        red[tid] = ksum;
        __syncthreads();
        if (tid < 128) red[tid] += red[tid + 128] + red[tid + 256];
        __syncthreads();
        for (int st = 64; st > 0; st >>= 1) {
            if (tid < st) red[tid] += red[tid + st];
            __syncthreads();
        }
        if (tid == 0)
            atomicAdd(&g_ksum[(bc / QKV) * INNER + (c - INNER)], red[0]);
    }
}

// ---------------- reciprocal of k-softmax sums ------------------------------
__global__ void krecip_kernel() {
    int i = blockIdx.x * blockDim.x + threadIdx.x;   // 0..2047
    g_krsum[i] = 1.0f / g_ksum[i];
}

// ---------------- context = softmax_k^T @ v, partial over n-chunks ----------
__global__ void context_part_kernel() {
    int bh = blockIdx.x;
    int chunk = blockIdx.y;          // 0..8, 1024 positions each
    int b = bh / HEADS, h = bh % HEADS;
    const __half* kp = g_qkv2 + ((size_t)b * QKV + INNER + h * DH) * HW;
    const __half* vp = g_qkv2 + ((size_t)b * QKV + 2 * INNER + h * DH) * HW;
    const float* kr = g_krsum + b * INNER + h * DH;
    __shared__ float sk[DH][33];
    __shared__ float sv[DH][33];
    int t = threadIdx.x;             // 256
    int e = t & 31;
    int d0 = (t >> 5) * 4;
    float acc0 = 0.f, acc1 = 0.f, acc2 = 0.f, acc3 = 0.f;
    int nbeg = chunk * 1024, nend = nbeg + 1024;
    for (int n0 = nbeg; n0 < nend; n0 += 32) {
        #pragma unroll
        for (int i = 0; i < 4; i++) {
            int idx = t + i * 256;
            int d = idx >> 5, nn = idx & 31;
            float kv = __half2float(kp[(size_t)d * HW + n0 + nn]);
            sk[d][nn] = __expf(kv) * kr[d];
            sv[d][nn] = __half2float(vp[(size_t)d * HW + n0 + nn]);
        }
        __syncthreads();
        #pragma unroll
        for (int nn = 0; nn < 32; nn++) {
            float vv = sv[e][nn];
            acc0 += sk[d0 + 0][nn] * vv;
            acc1 += sk[d0 + 1][nn] * vv;
            acc2 += sk[d0 + 2][nn] * vv;
            acc3 += sk[d0 + 3][nn] * vv;
        }
        __syncthreads();
    }
    float* cp = g_ctxp + ((size_t)chunk * BATCH * HEADS + bh) * DH * DH;
    cp[(d0 + 0) * DH + e] = acc0;
    cp[(d0 + 1) * DH + e] = acc1;
    cp[(d0 + 2) * DH + e] = acc2;
    cp[(d0 + 3) * DH + e] = acc3;
}

// ---------------- q softmax @ context + silu -> fp16 (inline ctx reduce) ----
__global__ void qattn_kernel() {
    int bh = blockIdx.y;
    int b = bh / HEADS, h = bh % HEADS;
    int n = blockIdx.x * 256 + threadIdx.x;
    __shared__ float sctx[DH][DH];
    for (int i = threadIdx.x; i < DH * DH; i += 256) {
        float ssum = 0.f;
        #pragma unroll
        for (int cc = 0; cc < 9; cc++)
            ssum += g_ctxp[((size_t)cc * BATCH * HEADS + bh) * DH * DH + i];
        sctx[i / DH][i % DH] = ssum;
    }
    __syncthreads();
    const __half* qp = g_qkv2 + ((size_t)b * QKV + h * DH) * HW + n;
    float qv[DH];
    float m = -1e30f;
    #pragma unroll
    for (int d = 0; d < DH; d++) {
        qv[d] = __half2float(qp[(size_t)d * HW]);
        m = fmaxf(m, qv[d]);
    }
    float sum = 0.f;
    #pragma unroll
    for (int d = 0; d < DH; d++) { qv[d] = __expf(qv[d] - m); sum += qv[d]; }
    float sc = 0.17677669529663688f / sum;  // (1/sqrt(32)) / sum
    #pragma unroll
    for (int d = 0; d < DH; d++) qv[d] *= sc;
    size_t obase = ((size_t)b * INNER + h * DH) * HW + n;
    #pragma unroll
    for (int e = 0; e < DH; e++) {
        float o = 0.f;
        #pragma unroll
        for (int d = 0; d < DH; d++) o += qv[d] * sctx[d][e];
        o = o / (1.0f + __expf(-o));   // silu
        g_af[obase + (size_t)e * HW] = __float2half(o);
    }
}

// ---------------- launch ----------------------------------------------------
extern "C" void kernel_launch(void* const* d_in, const int* in_sizes, int n_in,
                              void* d_out, int out_size) {
    const float* fmap       = (const float*)d_in[0];
    const float* norm_g     = (const float*)d_in[1];
    const float* q_w1       = (const float*)d_in[2];
    const float* q_wd       = (const float*)d_in[3];
    const float* k_w1       = (const float*)d_in[4];
    const float* k_wd       = (const float*)d_in[5];
    const float* v_w1       = (const float*)d_in[6];
    const float* v_wd       = (const float*)d_in[7];
    const float* out_w      = (const float*)d_in[8];
    const float* out_norm_g = (const float*)d_in[9];
    float* out = (float*)d_out;

    // gemm1 smem: 2 stages * (128*72 + 64*136) halves * 2B = 71680
    const int GEMM1_SMEM = 2 * (128 * 72 + 64 * 136) * 2;
    // gemm2 smem: 2 stages * (512*72 + 64*40) halves * 2B = 157696
    const int GEMM2_SMEM = 2 * (512 * 72 + 64 * 40) * 2;
    const int LN_SMEM = 512 * 33 * 4;   // 67584
    cudaFuncSetAttribute(gemm_qkv_kernel,
                         cudaFuncAttributeMaxDynamicSharedMemorySize, GEMM1_SMEM);
    cudaFuncSetAttribute(gemm_out_ln_kernel,
                         cudaFuncAttributeMaxDynamicSharedMemorySize, GEMM2_SMEM);
    cudaFuncSetAttribute(ln_in_kernel,
                         cudaFuncAttributeMaxDynamicSharedMemorySize, LN_SMEM);

    // fp16 weights + g_ksum zeroing (runs first every replay)
    convert_w_kernel<<<(INNER * CDIM) / 256, 256>>>(q_w1, k_w1, v_w1, out_w);

    // input LN -> fp16 plane (single pass)
    ln_in_kernel<<<(BATCH * HW) / 32, 256, LN_SMEM>>>(fmap, norm_g);

    // qkv = Wqkv @ xn  (tensor cores, fp16 output)
    gemm_qkv_kernel<<<dim3(HW / 128, QKV / 128, BATCH), 256, GEMM1_SMEM>>>();

    // depthwise 3x3 (fp16 raw smem, rolling window) + fused k-softmax sum
    dwconv3_kernel<<<dim3(BATCH * QKV, 2), dim3(96, 4)>>>(q_wd, k_wd, v_wd);

    // attention
    krecip_kernel<<<(BATCH * INNER) / 256, 256>>>();
    context_part_kernel<<<dim3(BATCH * HEADS, 9), 256>>>();
    qattn_kernel<<<dim3(HW / 256, BATCH * HEADS), 256>>>();

    // out projection + final LN fused (writes d_out directly)
    gemm_out_ln_kernel<<<dim3(HW / 32, BATCH), 256, GEMM2_SMEM>>>(out_norm_g, out);
}

// round 16
// speedup vs baseline: 1.0282x; 1.0282x over previous
#include <cuda_runtime.h>
#include <cuda_bf16.h>
#include <cuda_fp16.h>
#include <math.h>
#include <stdint.h>

#define BATCH 8
#define CDIM  512
#define INNER 256
#define QKV   768
#define HEADS 8
#define DH    32
#define HH    96
#define WW    96
#define HW    9216   // 96*96

// ---------------- scratch (static device globals) ---------------------------
__device__ __half g_xf  [(size_t)BATCH * CDIM  * HW];   // LN(x) fp16
__device__ __half g_qkv1[(size_t)BATCH * QKV   * HW];   // after 1x1 (fp16)
__device__ __half g_qkv2[(size_t)BATCH * QKV   * HW];   // after dwconv3 (fp16)
__device__ __half g_af  [(size_t)BATCH * INNER * HW];   // attn+silu fp16
__device__ float g_z    [(size_t)BATCH * CDIM  * HW];   // after out conv1x1 (fp32!)
__device__ __half g_wh  [(size_t)QKV * CDIM];           // qkv weights fp16
__device__ __half g_owh [(size_t)CDIM * INNER];         // out weights fp16
__device__ float g_ksum [BATCH * INNER];
__device__ float g_ctxp [(size_t)9 * BATCH * HEADS * DH * DH];

// ---------------- merged weight conversion + ksum zeroing -------------------
__global__ void convert_w_kernel(const float* __restrict__ qw,
                                 const float* __restrict__ kw,
                                 const float* __restrict__ vw,
                                 const float* __restrict__ ow) {
    int i = blockIdx.x * blockDim.x + threadIdx.x;  // 0 .. INNER*CDIM-1
    g_wh[i]                 = __float2half(qw[i]);
    g_wh[i + INNER*CDIM]    = __float2half(kw[i]);
    g_wh[i + 2*INNER*CDIM]  = __float2half(vw[i]);
    g_owh[i]                = __float2half(ow[i]);    // CDIM*INNER == INNER*CDIM
    if (i < BATCH * INNER) g_ksum[i] = 0.f;           // zero each replay
}

// ---------------- input channel LN (smem-buffered, single pass) -------------
__global__ void ln_in_kernel(const float* __restrict__ x,
                             const float* __restrict__ g) {
    extern __shared__ float s[];            // [512][33]
    __shared__ float s_mean[32], s_r[32];
    int t = threadIdx.x;
    int pos0 = blockIdx.x * 32;
    int b = pos0 / HW;
    int hw0 = pos0 - b * HW;
    int lane = t & 31, crow = t >> 5;
    #pragma unroll 8
    for (int it = 0; it < 64; it++) {
        int c = crow + it * 8;
        s[c * 33 + lane] = x[((size_t)b * CDIM + c) * HW + hw0 + lane];
    }
    __syncthreads();
    int p = t >> 3, sub = t & 7;            // 8 threads per position
    float sm = 0.f, sq = 0.f;
    #pragma unroll 8
    for (int j = 0; j < 64; j++) {
        float v = s[(sub + j * 8) * 33 + p];
        sm += v; sq += v * v;
    }
    #pragma unroll
    for (int off = 4; off > 0; off >>= 1) {
        sm += __shfl_xor_sync(0xffffffffu, sm, off);
        sq += __shfl_xor_sync(0xffffffffu, sq, off);
    }
    float mean = sm * (1.f / CDIM);
    float var  = sq * (1.f / CDIM) - mean * mean;
    float r = rsqrtf(var + 1e-5f);
    if (sub == 0) { s_mean[p] = mean; s_r[p] = r; }
    __syncthreads();
    float m2 = s_mean[lane], r2 = s_r[lane];
    #pragma unroll 8
    for (int it = 0; it < 64; it++) {
        int c = crow + it * 8;
        float y = (s[c * 33 + lane] - m2) * r2 * g[c];
        g_xf[((size_t)b * CDIM + c) * HW + hw0 + lane] = __float2half(y);
    }
}

// ---------------- output channel LN (fp32 z -> fp32 out, single pass) -------
__global__ void ln_out_kernel(const float* __restrict__ g,
                              float* __restrict__ out) {
    extern __shared__ float s[];            // [512][33]
    __shared__ float s_mean[32], s_r[32];
    int t = threadIdx.x;
    int pos0 = blockIdx.x * 32;
    int b = pos0 / HW;
    int hw0 = pos0 - b * HW;
    int lane = t & 31, crow = t >> 5;
    #pragma unroll 8
    for (int it = 0; it < 64; it++) {
        int c = crow + it * 8;
        s[c * 33 + lane] = g_z[((size_t)b * CDIM + c) * HW + hw0 + lane];
    }
    __syncthreads();
    int p = t >> 3, sub = t & 7;
    float sm = 0.f, sq = 0.f;
    #pragma unroll 8
    for (int j = 0; j < 64; j++) {
        float v = s[(sub + j * 8) * 33 + p];
        sm += v; sq += v * v;
    }
    #pragma unroll
    for (int off = 4; off > 0; off >>= 1) {
        sm += __shfl_xor_sync(0xffffffffu, sm, off);
        sq += __shfl_xor_sync(0xffffffffu, sq, off);
    }
    float mean = sm * (1.f / CDIM);
    float var  = sq * (1.f / CDIM) - mean * mean;
    float r = rsqrtf(var + 1e-5f);
    if (sub == 0) { s_mean[p] = mean; s_r[p] = r; }
    __syncthreads();
    float m2 = s_mean[lane], r2 = s_r[lane];
    #pragma unroll 8
    for (int it = 0; it < 64; it++) {
        int c = crow + it * 8;
        out[((size_t)b * CDIM + c) * HW + hw0 + lane] =
            (s[c * 33 + lane] - m2) * r2 * g[c];
    }
}

// ---------------- tensor-core GEMM (single fp16 weight plane, BK=64) --------
__device__ __forceinline__ uint32_t sptr(const void* p) {
    return (uint32_t)__cvta_generic_to_shared(p);
}
__device__ __forceinline__ void cp_async16(void* sm, const void* gm) {
    asm volatile("cp.async.cg.shared.global [%0], [%1], 16;\n"
                 :: "r"(sptr(sm)), "l"(gm));
}
__device__ __forceinline__ void ldsm_x4(uint32_t* r, uint32_t a) {
    asm volatile("ldmatrix.sync.aligned.m8n8.x4.shared.b16 {%0,%1,%2,%3}, [%4];"
                 : "=r"(r[0]), "=r"(r[1]), "=r"(r[2]), "=r"(r[3]) : "r"(a));
}
__device__ __forceinline__ void ldsm_x2t(uint32_t* r, uint32_t a) {
    asm volatile("ldmatrix.sync.aligned.m8n8.x2.trans.shared.b16 {%0,%1}, [%2];"
                 : "=r"(r[0]), "=r"(r[1]) : "r"(a));
}
__device__ __forceinline__ void mma_f16(float* c, const uint32_t* a, const uint32_t* b) {
    asm volatile("mma.sync.aligned.m16n8k16.row.col.f32.f16.f16.f32 "
                 "{%0,%1,%2,%3},{%4,%5,%6,%7},{%8,%9},{%0,%1,%2,%3};"
                 : "+f"(c[0]), "+f"(c[1]), "+f"(c[2]), "+f"(c[3])
                 : "r"(a[0]), "r"(a[1]), "r"(a[2]), "r"(a[3]), "r"(b[0]), "r"(b[1]));
}

template<int M, int K, typename OutT>
__device__ __forceinline__ void mma_gemm_body(const __half* __restrict__ W,
                                              const __half* __restrict__ Xf,
                                              OutT* __restrict__ Y) {
    constexpr int N = HW;
    constexpr int BM = 128, BN = 128, BK = 64;
    constexpr int AP = BK + 8;      // 72 halves/row (144B): conflict-free ldsm
    constexpr int BP = BN + 8;      // 136 halves/row (272B)
    constexpr int A_SZ = BM * AP;   // 9216 halves
    constexpr int B_SZ = BK * BP;   // 8704 halves
    constexpr int STAGE = A_SZ + B_SZ;   // 17920 halves = 35840 B
    constexpr int KC = K / BK;
    extern __shared__ __half smem[];

    int b = blockIdx.z;
    const __half* XfB = Xf + (size_t)b * K * N;
    OutT* Yb = Y + (size_t)b * M * N;
    int tm0 = blockIdx.y * BM;
    int tn0 = blockIdx.x * BN;
    int t = threadIdx.x;
    int lane = t & 31, warp = t >> 5;
    int wm = (warp & 1) * 64, wn = (warp >> 1) * 32;

    auto load_stage = [&](int kc, int s) {
        __half* sa = smem + (size_t)s * STAGE;
        __half* sb = sa + A_SZ;
        int k0 = kc * BK;
        #pragma unroll
        for (int i = 0; i < 4; i++) {
            int c = t + i * 256;            // 0..1023
            int m  = c >> 3, kk = (c & 7) * 8;
            cp_async16(&sa[m * AP + kk], &W[(size_t)(tm0 + m) * K + k0 + kk]);
            int kr = c >> 4, nn = (c & 15) * 8;
            cp_async16(&sb[kr * BP + nn], &XfB[(size_t)(k0 + kr) * N + tn0 + nn]);
        }
        asm volatile("cp.async.commit_group;");
    };

    float acc[4][4][4];
    #pragma unroll
    for (int i = 0; i < 4; i++)
        #pragma unroll
        for (int j = 0; j < 4; j++)
            #pragma unroll
            for (int r = 0; r < 4; r++) acc[i][j][r] = 0.f;

    load_stage(0, 0);
    for (int kc = 0; kc < KC; kc++) {
        int s = kc & 1;
        asm volatile("cp.async.wait_group 0;");
        __syncthreads();
        if (kc + 1 < KC) load_stage(kc + 1, s ^ 1);

        __half* sa = smem + (size_t)s * STAGE;
        __half* sb = sa + A_SZ;

        #pragma unroll
        for (int ks = 0; ks < 4; ks++) {
            uint32_t bx[4][2];
            int brow = ks * 16 + (lane & 15);
            #pragma unroll
            for (int nt = 0; nt < 4; nt++)
                ldsm_x2t(bx[nt], sptr(&sb[brow * BP + wn + nt * 8]));
            uint32_t a[4][4];
            int arow = lane & 15;
            int acol = ks * 16 + (lane >> 4) * 8;
            #pragma unroll
            for (int mt = 0; mt < 4; mt++)
                ldsm_x4(a[mt], sptr(&sa[(wm + mt * 16 + arow) * AP + acol]));
            #pragma unroll
            for (int mt = 0; mt < 4; mt++)
                #pragma unroll
                for (int nt = 0; nt < 4; nt++)
                    mma_f16(acc[mt][nt], a[mt], bx[nt]);
        }
    }

    #pragma unroll
    for (int mt = 0; mt < 4; mt++)
        #pragma unroll
        for (int nt = 0; nt < 4; nt++) {
            int m = tm0 + wm + mt * 16 + (lane >> 2);
            int n = tn0 + wn + nt * 8 + (lane & 3) * 2;
            if constexpr (sizeof(OutT) == 2) {
                *(__half2*)&Yb[(size_t)m * N + n] =
                    __floats2half2_rn(acc[mt][nt][0], acc[mt][nt][1]);
                *(__half2*)&Yb[(size_t)(m + 8) * N + n] =
                    __floats2half2_rn(acc[mt][nt][2], acc[mt][nt][3]);
            } else {
                *(float2*)&Yb[(size_t)m * N + n]       = make_float2(acc[mt][nt][0], acc[mt][nt][1]);
                *(float2*)&Yb[(size_t)(m + 8) * N + n] = make_float2(acc[mt][nt][2], acc[mt][nt][3]);
            }
        }
}

__global__ void __launch_bounds__(256) gemm_qkv_kernel() {
    mma_gemm_body<QKV, CDIM, __half>(g_wh, g_xf, g_qkv1);
}
__global__ void __launch_bounds__(256) gemm_out_kernel() {
    mma_gemm_body<CDIM, INNER, float>(g_owh, g_af, g_z);
}

// ---------------- depthwise 3x3: fp16 raw smem, rolling window, fused ksum --
__global__ void dwconv3_kernel(const float* __restrict__ qwd,
                               const float* __restrict__ kwd,
                               const float* __restrict__ vwd) {
    __shared__ __half s[50][112];
    __shared__ float red[384];
    int bc = blockIdx.x;              // b*QKV + c
    int half_id = blockIdx.y;         // 0: rows 0-47, 1: rows 48-95
    int h0 = half_id * 48;
    int c = bc % QKV;
    const float* wp = (c < 256) ? (qwd + c * 9)
                    : (c < 512) ? (kwd + (c - 256) * 9)
                                : (vwd + (c - 512) * 9);
    float w0 = wp[0], w1 = wp[1], w2 = wp[2];
    float w3 = wp[3], w4 = wp[4], w5 = wp[5];
    float w6 = wp[6], w7 = wp[7], w8 = wp[8];
    const __half* ip = g_qkv1 + (size_t)bc * HW;
    int tx = threadIdx.x;  // 0..95
    int ty = threadIdx.y;  // 0..3
    int tid = ty * 96 + tx;

    __half hz = __float2half(0.f);
    for (int r = tid; r < 50; r += 384) { s[r][7] = hz; s[r][104] = hz; }
    for (int i = tid; i < 50 * 12; i += 384) {
        int r = i / 12, c8 = i % 12;
        int hg = h0 - 1 + r;
        uint4* dst = (uint4*)&s[r][8 + c8 * 8];
        if (hg >= 0 && hg < HH) {
            *dst = *(const uint4*)(ip + (size_t)hg * WW + c8 * 8);
        } else {
            *dst = make_uint4(0u, 0u, 0u, 0u);
        }
    }
    __syncthreads();

    __half* op = g_qkv2 + (size_t)bc * HW + (size_t)h0 * WW;
    int wcol = 8 + tx;
    int base = ty * 12;               // local rows base..base+11
    bool is_k = (c >= INNER && c < 2 * INNER);
    float ksum = 0.f;

    float a0 = __half2float(s[base][wcol - 1]);
    float a1 = __half2float(s[base][wcol]);
    float a2 = __half2float(s[base][wcol + 1]);
    float b0 = __half2float(s[base + 1][wcol - 1]);
    float b1 = __half2float(s[base + 1][wcol]);
    float b2 = __half2float(s[base + 1][wcol + 1]);
    #pragma unroll
    for (int i = 0; i < 12; i++) {
        int hl = base + i;
        int r = hl + 2;
        float c0 = __half2float(s[r][wcol - 1]);
        float c1 = __half2float(s[r][wcol]);
        float c2 = __half2float(s[r][wcol + 1]);
        float acc = w0 * a0 + w1 * a1 + w2 * a2
                  + w3 * b0 + w4 * b1 + w5 * b2
                  + w6 * c0 + w7 * c1 + w8 * c2;
        __half hacc = __float2half(acc);
        op[hl * WW + tx] = hacc;
        if (is_k) ksum += __expf(__half2float(hacc));   // consistent with reader
        a0 = b0; a1 = b1; a2 = b2;
        b0 = c0; b1 = c1; b2 = c2;
    }

    if (is_k) {
        red[tid] = ksum;
        __syncthreads();
        if (tid < 128) red[tid] += red[tid + 128] + red[tid + 256];
        __syncthreads();
        for (int st = 64; st > 0; st >>= 1) {
            if (tid < st) red[tid] += red[tid + st];
            __syncthreads();
        }
        if (tid == 0)
            atomicAdd(&g_ksum[(bc / QKV) * INNER + (c - INNER)], red[0]);
    }
}

// ---------------- context = softmax_k^T @ v, partial over n-chunks ----------
// (krecip folded in: per-block 1/sum into smem, bit-identical weights)
__global__ void context_part_kernel() {
    int bh = blockIdx.x;
    int chunk = blockIdx.y;          // 0..8, 1024 positions each
    int b = bh / HEADS, h = bh % HEADS;
    const __half* kp = g_qkv2 + ((size_t)b * QKV + INNER + h * DH) * HW;
    const __half* vp = g_qkv2 + ((size_t)b * QKV + 2 * INNER + h * DH) * HW;
    __shared__ float sk[DH][33];
    __shared__ float sv[DH][33];
    __shared__ float skr[DH];
    int t = threadIdx.x;             // 256
    if (t < DH) skr[t] = 1.0f / g_ksum[b * INNER + h * DH + t];
    __syncthreads();
    int e = t & 31;
    int d0 = (t >> 5) * 4;
    float acc0 = 0.f, acc1 = 0.f, acc2 = 0.f, acc3 = 0.f;
    int nbeg = chunk * 1024, nend = nbeg + 1024;
    for (int n0 = nbeg; n0 < nend; n0 += 32) {
        #pragma unroll
        for (int i = 0; i < 4; i++) {
            int idx = t + i * 256;
            int d = idx >> 5, nn = idx & 31;
            float kv = __half2float(kp[(size_t)d * HW + n0 + nn]);
            sk[d][nn] = __expf(kv) * skr[d];
            sv[d][nn] = __half2float(vp[(size_t)d * HW + n0 + nn]);
        }
        __syncthreads();
        #pragma unroll
        for (int nn = 0; nn < 32; nn++) {
            float vv = sv[e][nn];
            acc0 += sk[d0 + 0][nn] * vv;
            acc1 += sk[d0 + 1][nn] * vv;
            acc2 += sk[d0 + 2][nn] * vv;
            acc3 += sk[d0 + 3][nn] * vv;
        }
        __syncthreads();
    }
    float* cp = g_ctxp + ((size_t)chunk * BATCH * HEADS + bh) * DH * DH;
    cp[(d0 + 0) * DH + e] = acc0;
    cp[(d0 + 1) * DH + e] = acc1;
    cp[(d0 + 2) * DH + e] = acc2;
    cp[(d0 + 3) * DH + e] = acc3;
}

// ---------------- q softmax @ context + silu -> fp16 (inline ctx reduce) ----
__global__ void qattn_kernel() {
    int bh = blockIdx.y;
    int b = bh / HEADS, h = bh % HEADS;
    int n = blockIdx.x * 256 + threadIdx.x;
    __shared__ float sctx[DH][DH];
    for (int i = threadIdx.x; i < DH * DH; i += 256) {
        float ssum = 0.f;
        #pragma unroll
        for (int cc = 0; cc < 9; cc++)
            ssum += g_ctxp[((size_t)cc * BATCH * HEADS + bh) * DH * DH + i];
        sctx[i / DH][i % DH] = ssum;
    }
    __syncthreads();
    const __half* qp = g_qkv2 + ((size_t)b * QKV + h * DH) * HW + n;
    float qv[DH];
    float m = -1e30f;
    #pragma unroll
    for (int d = 0; d < DH; d++) {
        qv[d] = __half2float(qp[(size_t)d * HW]);
        m = fmaxf(m, qv[d]);
    }
    float sum = 0.f;
    #pragma unroll
    for (int d = 0; d < DH; d++) { qv[d] = __expf(qv[d] - m); sum += qv[d]; }
    float sc = 0.17677669529663688f / sum;  // (1/sqrt(32)) / sum
    #pragma unroll
    for (int d = 0; d < DH; d++) qv[d] *= sc;
    size_t obase = ((size_t)b * INNER + h * DH) * HW + n;
    #pragma unroll
    for (int e = 0; e < DH; e++) {
        float o = 0.f;
        #pragma unroll
        for (int d = 0; d < DH; d++) o += qv[d] * sctx[d][e];
        o = o / (1.0f + __expf(-o));   // silu
        g_af[obase + (size_t)e * HW] = __float2half(o);
    }
}

// ---------------- launch ----------------------------------------------------
extern "C" void kernel_launch(void* const* d_in, const int* in_sizes, int n_in,
                              void* d_out, int out_size) {
    const float* fmap       = (const float*)d_in[0];
    const float* norm_g     = (const float*)d_in[1];
    const float* q_w1       = (const float*)d_in[2];
    const float* q_wd       = (const float*)d_in[3];
    const float* k_w1       = (const float*)d_in[4];
    const float* k_wd       = (const float*)d_in[5];
    const float* v_w1       = (const float*)d_in[6];
    const float* v_wd       = (const float*)d_in[7];
    const float* out_w      = (const float*)d_in[8];
    const float* out_norm_g = (const float*)d_in[9];
    float* out = (float*)d_out;

    // GEMM smem: 2 stages * (128*72 + 64*136) halves * 2B = 71680
    const int GEMM_SMEM = 2 * (128 * 72 + 64 * 136) * 2;
    const int LN_SMEM = 512 * 33 * 4;   // 67584
    cudaFuncSetAttribute(gemm_qkv_kernel,
                         cudaFuncAttributeMaxDynamicSharedMemorySize, GEMM_SMEM);
    cudaFuncSetAttribute(gemm_out_kernel,
                         cudaFuncAttributeMaxDynamicSharedMemorySize, GEMM_SMEM);
    cudaFuncSetAttribute(ln_in_kernel,
                         cudaFuncAttributeMaxDynamicSharedMemorySize, LN_SMEM);
    cudaFuncSetAttribute(ln_out_kernel,
                         cudaFuncAttributeMaxDynamicSharedMemorySize, LN_SMEM);

    // fp16 weights + g_ksum zeroing (runs first every replay)
    convert_w_kernel<<<(INNER * CDIM) / 256, 256>>>(q_w1, k_w1, v_w1, out_w);

    // input LN -> fp16 plane (single pass)
    ln_in_kernel<<<(BATCH * HW) / 32, 256, LN_SMEM>>>(fmap, norm_g);

    // qkv = Wqkv @ xn  (tensor cores, fp16 output)
    gemm_qkv_kernel<<<dim3(HW / 128, QKV / 128, BATCH), 256, GEMM_SMEM>>>();

    // depthwise 3x3 (fp16 raw smem, rolling window) + fused k-softmax sum
    dwconv3_kernel<<<dim3(BATCH * QKV, 2), dim3(96, 4)>>>(q_wd, k_wd, v_wd);

    // attention (krecip folded into context_part)
    context_part_kernel<<<dim3(BATCH * HEADS, 9), 256>>>();
    qattn_kernel<<<dim3(HW / 256, BATCH * HEADS), 256>>>();

    // out projection (tensor cores, fp32 output)
    gemm_out_kernel<<<dim3(HW / 128, CDIM / 128, BATCH), 256, GEMM_SMEM>>>();

    // final LN (fp32 z, single pass)
    ln_out_kernel<<<(BATCH * HW) / 32, 256, LN_SMEM>>>(out_norm_g, out);
}

// round 17
// speedup vs baseline: 1.1303x; 1.0993x over previous
#include <cuda_runtime.h>
#include <cuda_bf16.h>
#include <cuda_fp16.h>
#include <math.h>
#include <stdint.h>

#define BATCH 8
#define CDIM  512
#define INNER 256
#define QKV   768
#define HEADS 8
#define DH    32
#define HH    96
#define WW    96
#define HW    9216   // 96*96

// ---------------- scratch (static device globals) ---------------------------
__device__ __half g_xf  [(size_t)BATCH * CDIM  * HW];   // LN(x) fp16
__device__ __half g_qkv1[(size_t)BATCH * QKV   * HW];   // after 1x1 (fp16)
__device__ __half g_qkv2[(size_t)BATCH * QKV   * HW];   // after dwconv3 (fp16)
__device__ __half g_af  [(size_t)BATCH * INNER * HW];   // attn+silu fp16
__device__ __half g_wh  [(size_t)QKV * CDIM];           // qkv weights fp16
__device__ __half g_owh [(size_t)CDIM * INNER];         // out weights fp16
__device__ float g_ksum [BATCH * INNER];
__device__ float g_ctxp [(size_t)9 * BATCH * HEADS * DH * DH];

// ---------------- merged weight conversion + ksum zeroing -------------------
__global__ void convert_w_kernel(const float* __restrict__ qw,
                                 const float* __restrict__ kw,
                                 const float* __restrict__ vw,
                                 const float* __restrict__ ow) {
    int i = blockIdx.x * blockDim.x + threadIdx.x;  // 0 .. INNER*CDIM-1
    g_wh[i]                 = __float2half(qw[i]);
    g_wh[i + INNER*CDIM]    = __float2half(kw[i]);
    g_wh[i + 2*INNER*CDIM]  = __float2half(vw[i]);
    g_owh[i]                = __float2half(ow[i]);    // CDIM*INNER == INNER*CDIM
    if (i < BATCH * INNER) g_ksum[i] = 0.f;           // zero each replay
}

// ---------------- input channel LN (smem-buffered, single pass) -------------
__global__ void ln_in_kernel(const float* __restrict__ x,
                             const float* __restrict__ g) {
    extern __shared__ float s[];            // [512][33]
    __shared__ float s_mean[32], s_r[32];
    int t = threadIdx.x;
    int pos0 = blockIdx.x * 32;
    int b = pos0 / HW;
    int hw0 = pos0 - b * HW;
    int lane = t & 31, crow = t >> 5;
    #pragma unroll 8
    for (int it = 0; it < 64; it++) {
        int c = crow + it * 8;
        s[c * 33 + lane] = x[((size_t)b * CDIM + c) * HW + hw0 + lane];
    }
    __syncthreads();
    int p = t >> 3, sub = t & 7;            // 8 threads per position
    float sm = 0.f, sq = 0.f;
    #pragma unroll 8
    for (int j = 0; j < 64; j++) {
        float v = s[(sub + j * 8) * 33 + p];
        sm += v; sq += v * v;
    }
    #pragma unroll
    for (int off = 4; off > 0; off >>= 1) {
        sm += __shfl_xor_sync(0xffffffffu, sm, off);
        sq += __shfl_xor_sync(0xffffffffu, sq, off);
    }
    float mean = sm * (1.f / CDIM);
    float var  = sq * (1.f / CDIM) - mean * mean;
    float r = rsqrtf(var + 1e-5f);
    if (sub == 0) { s_mean[p] = mean; s_r[p] = r; }
    __syncthreads();
    float m2 = s_mean[lane], r2 = s_r[lane];
    #pragma unroll 8
    for (int it = 0; it < 64; it++) {
        int c = crow + it * 8;
        float y = (s[c * 33 + lane] - m2) * r2 * g[c];
        g_xf[((size_t)b * CDIM + c) * HW + hw0 + lane] = __float2half(y);
    }
}

// ---------------- shared GEMM helpers ---------------------------------------
__device__ __forceinline__ uint32_t sptr(const void* p) {
    return (uint32_t)__cvta_generic_to_shared(p);
}
__device__ __forceinline__ void cp_async16(void* sm, const void* gm) {
    asm volatile("cp.async.cg.shared.global [%0], [%1], 16;\n"
                 :: "r"(sptr(sm)), "l"(gm));
}
__device__ __forceinline__ void ldsm_x4(uint32_t* r, uint32_t a) {
    asm volatile("ldmatrix.sync.aligned.m8n8.x4.shared.b16 {%0,%1,%2,%3}, [%4];"
                 : "=r"(r[0]), "=r"(r[1]), "=r"(r[2]), "=r"(r[3]) : "r"(a));
}
__device__ __forceinline__ void ldsm_x2t(uint32_t* r, uint32_t a) {
    asm volatile("ldmatrix.sync.aligned.m8n8.x2.trans.shared.b16 {%0,%1}, [%2];"
                 : "=r"(r[0]), "=r"(r[1]) : "r"(a));
}
__device__ __forceinline__ void mma_f16(float* c, const uint32_t* a, const uint32_t* b) {
    asm volatile("mma.sync.aligned.m16n8k16.row.col.f32.f16.f16.f32 "
                 "{%0,%1,%2,%3},{%4,%5,%6,%7},{%8,%9},{%0,%1,%2,%3};"
                 : "+f"(c[0]), "+f"(c[1]), "+f"(c[2]), "+f"(c[3])
                 : "r"(a[0]), "r"(a[1]), "r"(a[2]), "r"(a[3]), "r"(b[0]), "r"(b[1]));
}

// ---------------- GEMM 1: qkv = W @ LN(x), tile 128x128x64, fp16 out --------
__global__ void __launch_bounds__(256) gemm_qkv_kernel() {
    constexpr int K = CDIM, N = HW;
    constexpr int BM = 128, BN = 128, BK = 64;
    constexpr int AP = BK + 8;      // 72
    constexpr int BP = BN + 8;      // 136
    constexpr int A_SZ = BM * AP;
    constexpr int B_SZ = BK * BP;
    constexpr int STAGE = A_SZ + B_SZ;
    constexpr int KC = K / BK;
    extern __shared__ __half smem[];

    int b = blockIdx.z;
    const __half* XfB = g_xf + (size_t)b * K * N;
    __half* Yb = g_qkv1 + (size_t)b * QKV * N;
    int tm0 = blockIdx.y * BM;
    int tn0 = blockIdx.x * BN;
    int t = threadIdx.x;
    int lane = t & 31, warp = t >> 5;
    int wm = (warp & 1) * 64, wn = (warp >> 1) * 32;

    auto load_stage = [&](int kc, int s) {
        __half* sa = smem + (size_t)s * STAGE;
        __half* sb = sa + A_SZ;
        int k0 = kc * BK;
        #pragma unroll
        for (int i = 0; i < 4; i++) {
            int c = t + i * 256;
            int m  = c >> 3, kk = (c & 7) * 8;
            cp_async16(&sa[m * AP + kk], &g_wh[(size_t)(tm0 + m) * K + k0 + kk]);
            int kr = c >> 4, nn = (c & 15) * 8;
            cp_async16(&sb[kr * BP + nn], &XfB[(size_t)(k0 + kr) * N + tn0 + nn]);
        }
        asm volatile("cp.async.commit_group;");
    };

    float acc[4][4][4];
    #pragma unroll
    for (int i = 0; i < 4; i++)
        #pragma unroll
        for (int j = 0; j < 4; j++)
            #pragma unroll
            for (int r = 0; r < 4; r++) acc[i][j][r] = 0.f;

    load_stage(0, 0);
    for (int kc = 0; kc < KC; kc++) {
        int s = kc & 1;
        asm volatile("cp.async.wait_group 0;");
        __syncthreads();
        if (kc + 1 < KC) load_stage(kc + 1, s ^ 1);

        __half* sa = smem + (size_t)s * STAGE;
        __half* sb = sa + A_SZ;

        #pragma unroll
        for (int ks = 0; ks < 4; ks++) {
            uint32_t bx[4][2];
            int brow = ks * 16 + (lane & 15);
            #pragma unroll
            for (int nt = 0; nt < 4; nt++)
                ldsm_x2t(bx[nt], sptr(&sb[brow * BP + wn + nt * 8]));
            uint32_t a[4][4];
            int arow = lane & 15;
            int acol = ks * 16 + (lane >> 4) * 8;
            #pragma unroll
            for (int mt = 0; mt < 4; mt++)
                ldsm_x4(a[mt], sptr(&sa[(wm + mt * 16 + arow) * AP + acol]));
            #pragma unroll
            for (int mt = 0; mt < 4; mt++)
                #pragma unroll
                for (int nt = 0; nt < 4; nt++)
                    mma_f16(acc[mt][nt], a[mt], bx[nt]);
        }
    }

    #pragma unroll
    for (int mt = 0; mt < 4; mt++)
        #pragma unroll
        for (int nt = 0; nt < 4; nt++) {
            int m = tm0 + wm + mt * 16 + (lane >> 2);
            int n = tn0 + wn + nt * 8 + (lane & 3) * 2;
            *(__half2*)&Yb[(size_t)m * N + n] =
                __floats2half2_rn(acc[mt][nt][0], acc[mt][nt][1]);
            *(__half2*)&Yb[(size_t)(m + 8) * N + n] =
                __floats2half2_rn(acc[mt][nt][2], acc[mt][nt][3]);
        }
}

// ---------------- GEMM 2 + output LN fused: tile 512x64x64, 512 threads -----
// 16 warps: warp w owns rows [w*32, w*32+32) x all 64 positions.
// LN over channels runs on the fp32 accumulators (z never hits HBM).
__global__ void __launch_bounds__(512) gemm_out_ln_kernel(
        const float* __restrict__ gamma, float* __restrict__ out) {
    constexpr int K = INNER, N = HW;
    constexpr int BM = 512, BN = 64, BK = 64;
    constexpr int AP = BK + 8;       // 72
    constexpr int BP = BN + 8;       // 72
    constexpr int A_SZ = BM * AP;    // 36864 halves
    constexpr int B_SZ = BK * BP;    // 4608 halves
    constexpr int STAGE = A_SZ + B_SZ;   // 41472 halves = 82944 B
    constexpr int KC = K / BK;       // 4
    extern __shared__ __half smem[];
    __shared__ float s_sum[16][64], s_sq[16][64];
    __shared__ float s_mean[64], s_rr[64];

    int b = blockIdx.y;
    int hw0 = blockIdx.x * BN;
    const __half* XfB = g_af + (size_t)b * K * N;
    int t = threadIdx.x, lane = t & 31, warp = t >> 5;
    int wm = warp * 32;

    auto load_stage = [&](int kc, int s) {
        __half* sa = smem + (size_t)s * STAGE;
        __half* sb = sa + A_SZ;
        int k0 = kc * BK;
        #pragma unroll
        for (int i = 0; i < 8; i++) {        // A: 4096 chunks
            int c = t + i * 512;
            int m = c >> 3, kk = (c & 7) * 8;
            cp_async16(&sa[m * AP + kk], &g_owh[(size_t)m * K + k0 + kk]);
        }
        {                                     // B: 512 chunks
            int kr = t >> 3, nn = (t & 7) * 8;
            cp_async16(&sb[kr * BP + nn], &XfB[(size_t)(k0 + kr) * N + hw0 + nn]);
        }
        asm volatile("cp.async.commit_group;");
    };

    float acc[2][8][4];
    #pragma unroll
    for (int i = 0; i < 2; i++)
        #pragma unroll
        for (int j = 0; j < 8; j++)
            #pragma unroll
            for (int r = 0; r < 4; r++) acc[i][j][r] = 0.f;

    load_stage(0, 0);
    for (int kc = 0; kc < KC; kc++) {
        int s = kc & 1;
        asm volatile("cp.async.wait_group 0;");
        __syncthreads();
        if (kc + 1 < KC) load_stage(kc + 1, s ^ 1);

        __half* sa = smem + (size_t)s * STAGE;
        __half* sb = sa + A_SZ;

        #pragma unroll
        for (int ks = 0; ks < 4; ks++) {
            uint32_t bx[8][2];
            int brow = ks * 16 + (lane & 15);
            #pragma unroll
            for (int nt = 0; nt < 8; nt++)
                ldsm_x2t(bx[nt], sptr(&sb[brow * BP + nt * 8]));
            uint32_t a[2][4];
            int arow = lane & 15;
            int acol = ks * 16 + (lane >> 4) * 8;
            #pragma unroll
            for (int mt = 0; mt < 2; mt++)
                ldsm_x4(a[mt], sptr(&sa[(wm + mt * 16 + arow) * AP + acol]));
            #pragma unroll
            for (int mt = 0; mt < 2; mt++)
                #pragma unroll
                for (int nt = 0; nt < 8; nt++)
                    mma_f16(acc[mt][nt], a[mt], bx[nt]);
        }
    }
    __syncthreads();

    // per-warp column sums (this warp's 32 rows) for sum and sumsq
    #pragma unroll
    for (int nt = 0; nt < 8; nt++) {
        float cs0 = 0.f, cs1 = 0.f, q0 = 0.f, q1 = 0.f;
        #pragma unroll
        for (int mt = 0; mt < 2; mt++) {
            float v0 = acc[mt][nt][0], v1 = acc[mt][nt][1];
            float v2 = acc[mt][nt][2], v3 = acc[mt][nt][3];
            cs0 += v0 + v2; cs1 += v1 + v3;
            q0  += v0 * v0 + v2 * v2;
            q1  += v1 * v1 + v3 * v3;
        }
        #pragma unroll
        for (int off = 4; off < 32; off <<= 1) {
            cs0 += __shfl_xor_sync(0xffffffffu, cs0, off);
            cs1 += __shfl_xor_sync(0xffffffffu, cs1, off);
            q0  += __shfl_xor_sync(0xffffffffu, q0 , off);
            q1  += __shfl_xor_sync(0xffffffffu, q1 , off);
        }
        if (lane < 4) {
            int col = nt * 8 + lane * 2;
            s_sum[warp][col]     = cs0;
            s_sum[warp][col + 1] = cs1;
            s_sq [warp][col]     = q0;
            s_sq [warp][col + 1] = q1;
        }
    }
    __syncthreads();
    if (t < 64) {
        float sm = 0.f, sq = 0.f;
        #pragma unroll
        for (int w = 0; w < 16; w++) { sm += s_sum[w][t]; sq += s_sq[w][t]; }
        float mean = sm * (1.f / CDIM);
        float var  = sq * (1.f / CDIM) - mean * mean;
        s_mean[t] = mean;
        s_rr[t]   = rsqrtf(var + 1e-5f);
    }
    __syncthreads();

    // normalize + write final output (fp32) straight from registers
    #pragma unroll
    for (int mt = 0; mt < 2; mt++) {
        int r0 = wm + mt * 16 + (lane >> 2);
        int r1 = r0 + 8;
        float g0 = gamma[r0], g1 = gamma[r1];
        #pragma unroll
        for (int nt = 0; nt < 8; nt++) {
            int n = nt * 8 + (lane & 3) * 2;
            float m0 = s_mean[n], m1 = s_mean[n + 1];
            float rr0 = s_rr[n],  rr1 = s_rr[n + 1];
            *(float2*)&out[((size_t)b * CDIM + r0) * HW + hw0 + n] =
                make_float2((acc[mt][nt][0] - m0) * rr0 * g0,
                            (acc[mt][nt][1] - m1) * rr1 * g0);
            *(float2*)&out[((size_t)b * CDIM + r1) * HW + hw0 + n] =
                make_float2((acc[mt][nt][2] - m0) * rr0 * g1,
                            (acc[mt][nt][3] - m1) * rr1 * g1);
        }
    }
}

// ---------------- depthwise 3x3: 2 cols/thread, half2 loads, fused ksum -----
__global__ void dwconv3_kernel(const float* __restrict__ qwd,
                               const float* __restrict__ kwd,
                               const float* __restrict__ vwd) {
    __shared__ __half s[50][112];
    __shared__ float red[384];
    int bc = blockIdx.x;              // b*QKV + c
    int half_id = blockIdx.y;         // 0: rows 0-47, 1: rows 48-95
    int h0 = half_id * 48;
    int c = bc % QKV;
    const float* wp = (c < 256) ? (qwd + c * 9)
                    : (c < 512) ? (kwd + (c - 256) * 9)
                                : (vwd + (c - 512) * 9);
    float w0 = wp[0], w1 = wp[1], w2 = wp[2];
    float w3 = wp[3], w4 = wp[4], w5 = wp[5];
    float w6 = wp[6], w7 = wp[7], w8 = wp[8];
    const __half* ip = g_qkv1 + (size_t)bc * HW;
    int tx = threadIdx.x;  // 0..47
    int ty = threadIdx.y;  // 0..7
    int tid = ty * 48 + tx;

    __half hz = __float2half(0.f);
    for (int r = tid; r < 50; r += 384) { s[r][7] = hz; s[r][104] = hz; }
    for (int i = tid; i < 50 * 12; i += 384) {
        int r = i / 12, c8 = i % 12;
        int hg = h0 - 1 + r;
        uint4* dst = (uint4*)&s[r][8 + c8 * 8];
        if (hg >= 0 && hg < HH) {
            *dst = *(const uint4*)(ip + (size_t)hg * WW + c8 * 8);
        } else {
            *dst = make_uint4(0u, 0u, 0u, 0u);
        }
    }
    __syncthreads();

    __half* op = g_qkv2 + (size_t)bc * HW + (size_t)h0 * WW;
    int wc = 8 + tx * 2;              // smem col of first output
    int base = ty * 6;                // local rows base..base+5
    bool is_k = (c >= INNER && c < 2 * INNER);
    float ksum = 0.f;

    // per row, cols wc-1..wc+2 via 3 aligned half2 loads
    float A[4], B[4], C[4];
    {
        __half2 p0 = *(__half2*)&s[base][wc - 2];
        __half2 p1 = *(__half2*)&s[base][wc];
        __half2 p2 = *(__half2*)&s[base][wc + 2];
        A[0] = __half2float(__high2half(p0));
        A[1] = __half2float(__low2half(p1));
        A[2] = __half2float(__high2half(p1));
        A[3] = __half2float(__low2half(p2));
        p0 = *(__half2*)&s[base + 1][wc - 2];
        p1 = *(__half2*)&s[base + 1][wc];
        p2 = *(__half2*)&s[base + 1][wc + 2];
        B[0] = __half2float(__high2half(p0));
        B[1] = __half2float(__low2half(p1));
        B[2] = __half2float(__high2half(p1));
        B[3] = __half2float(__low2half(p2));
    }
    #pragma unroll
    for (int i = 0; i < 6; i++) {
        int hl = base + i;
        int r = hl + 2;
        __half2 p0 = *(__half2*)&s[r][wc - 2];
        __half2 p1 = *(__half2*)&s[r][wc];
        __half2 p2 = *(__half2*)&s[r][wc + 2];
        C[0] = __half2float(__high2half(p0));
        C[1] = __half2float(__low2half(p1));
        C[2] = __half2float(__high2half(p1));
        C[3] = __half2float(__low2half(p2));
        float o0 = w0 * A[0] + w1 * A[1] + w2 * A[2]
                 + w3 * B[0] + w4 * B[1] + w5 * B[2]
                 + w6 * C[0] + w7 * C[1] + w8 * C[2];
        float o1 = w0 * A[1] + w1 * A[2] + w2 * A[3]
                 + w3 * B[1] + w4 * B[2] + w5 * B[3]
                 + w6 * C[1] + w7 * C[2] + w8 * C[3];
        __half ho0 = __float2half(o0);
        __half ho1 = __float2half(o1);
        *(__half2*)&op[hl * WW + tx * 2] = __halves2half2(ho0, ho1);
        if (is_k) ksum += __expf(__half2float(ho0)) + __expf(__half2float(ho1));
        A[0] = B[0]; A[1] = B[1]; A[2] = B[2]; A[3] = B[3];
        B[0] = C[0]; B[1] = C[1]; B[2] = C[2]; B[3] = C[3];
    }

    if (is_k) {
        red[tid] = ksum;
        __syncthreads();
        if (tid < 128) red[tid] += red[tid + 128] + red[tid + 256];
        __syncthreads();
        for (int st = 64; st > 0; st >>= 1) {
            if (tid < st) red[tid] += red[tid + st];
            __syncthreads();
        }
        if (tid == 0)
            atomicAdd(&g_ksum[(bc / QKV) * INNER + (c - INNER)], red[0]);
    }
}

// ---------------- context = softmax_k^T @ v, partial over n-chunks ----------
__global__ void context_part_kernel() {
    int bh = blockIdx.x;
    int chunk = blockIdx.y;          // 0..8, 1024 positions each
    int b = bh / HEADS, h = bh % HEADS;
    const __half* kp = g_qkv2 + ((size_t)b * QKV + INNER + h * DH) * HW;
    const __half* vp = g_qkv2 + ((size_t)b * QKV + 2 * INNER + h * DH) * HW;
    __shared__ float sk[DH][33];
    __shared__ float sv[DH][33];
    __shared__ float skr[DH];
    int t = threadIdx.x;             // 256
    if (t < DH) skr[t] = 1.0f / g_ksum[b * INNER + h * DH + t];
    __syncthreads();
    int e = t & 31;
    int d0 = (t >> 5) * 4;
    float acc0 = 0.f, acc1 = 0.f, acc2 = 0.f, acc3 = 0.f;
    int nbeg = chunk * 1024, nend = nbeg + 1024;
    for (int n0 = nbeg; n0 < nend; n0 += 32) {
        #pragma unroll
        for (int i = 0; i < 4; i++) {
            int idx = t + i * 256;
            int d = idx >> 5, nn = idx & 31;
            float kv = __half2float(kp[(size_t)d * HW + n0 + nn]);
            sk[d][nn] = __expf(kv) * skr[d];
            sv[d][nn] = __half2float(vp[(size_t)d * HW + n0 + nn]);
        }
        __syncthreads();
        #pragma unroll
        for (int nn = 0; nn < 32; nn++) {
            float vv = sv[e][nn];
            acc0 += sk[d0 + 0][nn] * vv;
            acc1 += sk[d0 + 1][nn] * vv;
            acc2 += sk[d0 + 2][nn] * vv;
            acc3 += sk[d0 + 3][nn] * vv;
        }
        __syncthreads();
    }
    float* cp = g_ctxp + ((size_t)chunk * BATCH * HEADS + bh) * DH * DH;
    cp[(d0 + 0) * DH + e] = acc0;
    cp[(d0 + 1) * DH + e] = acc1;
    cp[(d0 + 2) * DH + e] = acc2;
    cp[(d0 + 3) * DH + e] = acc3;
}

// ---------------- q softmax @ context + silu -> fp16 (inline ctx reduce) ----
__global__ void qattn_kernel() {
    int bh = blockIdx.y;
    int b = bh / HEADS, h = bh % HEADS;
    int n = blockIdx.x * 256 + threadIdx.x;
    __shared__ float sctx[DH][DH];
    for (int i = threadIdx.x; i < DH * DH; i += 256) {
        float ssum = 0.f;
        #pragma unroll
        for (int cc = 0; cc < 9; cc++)
            ssum += g_ctxp[((size_t)cc * BATCH * HEADS + bh) * DH * DH + i];
        sctx[i / DH][i % DH] = ssum;
    }
    __syncthreads();
    const __half* qp = g_qkv2 + ((size_t)b * QKV + h * DH) * HW + n;
    float qv[DH];
    float m = -1e30f;
    #pragma unroll
    for (int d = 0; d < DH; d++) {
        qv[d] = __half2float(qp[(size_t)d * HW]);
        m = fmaxf(m, qv[d]);
    }
    float sum = 0.f;
    #pragma unroll
    for (int d = 0; d < DH; d++) { qv[d] = __expf(qv[d] - m); sum += qv[d]; }
    float sc = 0.17677669529663688f / sum;  // (1/sqrt(32)) / sum
    #pragma unroll
    for (int d = 0; d < DH; d++) qv[d] *= sc;
    size_t obase = ((size_t)b * INNER + h * DH) * HW + n;
    #pragma unroll
    for (int e = 0; e < DH; e++) {
        float o = 0.f;
        #pragma unroll
        for (int d = 0; d < DH; d++) o += qv[d] * sctx[d][e];
        o = o / (1.0f + __expf(-o));   // silu
        g_af[obase + (size_t)e * HW] = __float2half(o);
    }
}

// ---------------- launch ----------------------------------------------------
extern "C" void kernel_launch(void* const* d_in, const int* in_sizes, int n_in,
                              void* d_out, int out_size) {
    const float* fmap       = (const float*)d_in[0];
    const float* norm_g     = (const float*)d_in[1];
    const float* q_w1       = (const float*)d_in[2];
    const float* q_wd       = (const float*)d_in[3];
    const float* k_w1       = (const float*)d_in[4];
    const float* k_wd       = (const float*)d_in[5];
    const float* v_w1       = (const float*)d_in[6];
    const float* v_wd       = (const float*)d_in[7];
    const float* out_w      = (const float*)d_in[8];
    const float* out_norm_g = (const float*)d_in[9];
    float* out = (float*)d_out;

    const int GEMM1_SMEM = 2 * (128 * 72 + 64 * 136) * 2;   // 71680
    const int GEMM2_SMEM = 2 * (512 * 72 + 64 * 72) * 2;    // 165888
    const int LN_SMEM = 512 * 33 * 4;                        // 67584
    cudaFuncSetAttribute(gemm_qkv_kernel,
                         cudaFuncAttributeMaxDynamicSharedMemorySize, GEMM1_SMEM);
    cudaFuncSetAttribute(gemm_out_ln_kernel,
                         cudaFuncAttributeMaxDynamicSharedMemorySize, GEMM2_SMEM);
    cudaFuncSetAttribute(ln_in_kernel,
                         cudaFuncAttributeMaxDynamicSharedMemorySize, LN_SMEM);

    // fp16 weights + g_ksum zeroing (runs first every replay)
    convert_w_kernel<<<(INNER * CDIM) / 256, 256>>>(q_w1, k_w1, v_w1, out_w);

    // input LN -> fp16 plane (single pass)
    ln_in_kernel<<<(BATCH * HW) / 32, 256, LN_SMEM>>>(fmap, norm_g);

    // qkv = Wqkv @ xn  (tensor cores, fp16 output)
    gemm_qkv_kernel<<<dim3(HW / 128, QKV / 128, BATCH), 256, GEMM1_SMEM>>>();

    // depthwise 3x3 (2 cols/thread) + fused k-softmax sum
    dwconv3_kernel<<<dim3(BATCH * QKV, 2), dim3(48, 8)>>>(q_wd, k_wd, v_wd);

    // attention
    context_part_kernel<<<dim3(BATCH * HEADS, 9), 256>>>();
    qattn_kernel<<<dim3(HW / 256, BATCH * HEADS), 256>>>();

    // out projection + final LN fused in registers (writes d_out directly)
    gemm_out_ln_kernel<<<dim3(HW / 64, BATCH), 512, GEMM2_SMEM>>>(out_norm_g, out);
}